// round 3
// baseline (speedup 1.0000x reference)
#include <cuda_runtime.h>
#include <cstdint>

// Problem constants (fixed by the reference): x is (8, 256, 256, 32) fp32,
// WINDOW=3, PAD=1, reflect padding (no edge repeat).
// out[b,h,w, c*9 + i] = x[b, reflect(h+i/3-1), reflect(w+i%3-1), c]
// i.e. per pixel: a 9x32 -> 32x9 transpose of the neighborhood channel vectors.

static constexpr int B = 8;
static constexpr int H = 256;
static constexpr int W = 256;
static constexpr int C = 32;           // == warp size: lane = channel
static constexpr int TAPS = 9;
static constexpr int OUT_PER_PIX = C * TAPS;          // 288 floats = 1152 B
static constexpr int WARPS_PER_BLOCK = 8;
static constexpr int THREADS = WARPS_PER_BLOCK * 32;  // 256

__global__ __launch_bounds__(THREADS)
void patch_extract_kernel(const float* __restrict__ x, float* __restrict__ out) {
    const int warp_in_blk = threadIdx.x >> 5;
    const int lane        = threadIdx.x & 31;
    const long long pix   = (long long)blockIdx.x * WARPS_PER_BLOCK + warp_in_blk;
    // pix = (b*H + h)*W + w
    const int w  = (int)(pix % W);
    const int hw = (int)(pix / W);
    const int h  = hw % H;
    const int b  = hw / H;

    // Per-warp 288-float transpose staging. Stride-9 word indexing is a
    // permutation mod 32 banks -> conflict-free STS.
    __shared__ __align__(16) float sm[WARPS_PER_BLOCK][OUT_PER_PIX];
    float* s = sm[warp_in_blk];

    // Reflected neighbor rows/cols (PAD=1; -1 -> 1, N -> N-2).
    int rh[3], rw[3];
#pragma unroll
    for (int d = 0; d < 3; d++) {
        int r = h + d - 1;
        rh[d] = (r < 0) ? 1 : ((r >= H) ? H - 2 : r);
        int cc = w + d - 1;
        rw[d] = (cc < 0) ? 1 : ((cc >= W) ? W - 2 : cc);
    }

    const float* xb = x + (size_t)b * H * W * C;

    // 9 fully-coalesced 128B line loads (lane = channel), scatter into smem
    // in output order: s[c*9 + i].
#pragma unroll
    for (int i = 0; i < TAPS; i++) {
        const int di = i / 3;
        const int dj = i % 3;
        const float v = xb[((size_t)rh[di] * W + rw[dj]) * C + lane];
        s[lane * TAPS + i] = v;
    }
    __syncwarp();

    // Coalesced 128-bit stores of the 1152B output block for this pixel.
    float4* __restrict__ out4 = reinterpret_cast<float4*>(out + (size_t)pix * OUT_PER_PIX);
    const float4* __restrict__ s4 = reinterpret_cast<const float4*>(s);
#pragma unroll
    for (int j = lane; j < OUT_PER_PIX / 4; j += 32) {  // 72 float4
        out4[j] = s4[j];
    }
}

extern "C" void kernel_launch(void* const* d_in, const int* in_sizes, int n_in,
                              void* d_out, int out_size) {
    const float* x = (const float*)d_in[0];
    float* out = (float*)d_out;
    (void)in_sizes; (void)n_in; (void)out_size;

    const long long n_pix = (long long)B * H * W;       // 524288
    const int blocks = (int)(n_pix / WARPS_PER_BLOCK);  // 65536
    patch_extract_kernel<<<blocks, THREADS>>>(x, out);
}

// round 4
// speedup vs baseline: 1.2423x; 1.2423x over previous
#include <cuda_runtime.h>
#include <cstdint>

// x: (8, 256, 256, 32) fp32, reflect-pad 3x3 patch extraction.
// out[b,h,w, c*9 + i] = x[b, reflect(h + i/3 - 1), reflect(w + i%3 - 1), c]
//
// Warp = 4-pixel strip along W. Loads a 3x6 tap tile (18 coalesced 128B line
// loads, lane = channel), transposes through smem (stride-9 word scatter is
// bank-conflict-free), stores 4*1152B contiguous via 9 full-warp STG.128
// iterations with streaming (.cs) hint.

static constexpr int B = 8;
static constexpr int H = 256;
static constexpr int W = 256;
static constexpr int C = 32;
static constexpr int TAPS = 9;
static constexpr int OUT_PER_PIX = C * TAPS;   // 288 floats = 1152 B
static constexpr int PIX_PER_WARP = 4;
static constexpr int WARPS_PER_BLOCK = 8;
static constexpr int THREADS = WARPS_PER_BLOCK * 32;

__global__ __launch_bounds__(THREADS)
void patch_extract_kernel(const float* __restrict__ x, float* __restrict__ out) {
    const int warp = threadIdx.x >> 5;
    const int lane = threadIdx.x & 31;

    // blockIdx.y = b*H + h  (2048 rows); blockIdx.x = strip-group (8 per row)
    const int h = blockIdx.y & (H - 1);
    const int b = blockIdx.y >> 8;
    const int strip = blockIdx.x * WARPS_PER_BLOCK + warp;
    const int w0 = strip * PIX_PER_WARP;       // first pixel of the strip

    // Per-warp staging: 4 pixels x 288 floats = 4608 B.
    __shared__ __align__(16) float sm[WARPS_PER_BLOCK][PIX_PER_WARP * OUT_PER_PIX];
    float* s = sm[warp];

    // Reflected rows (3) and columns (6: w0-1 .. w0+4). PAD=1: -1 -> 1, N -> N-2.
    int rh[3];
#pragma unroll
    for (int d = 0; d < 3; d++) {
        int r = h + d - 1;
        rh[d] = (r < 0) ? 1 : ((r >= H) ? H - 2 : r);
    }
    int rw[6];
#pragma unroll
    for (int t = 0; t < 6; t++) {
        int cc = w0 - 1 + t;
        rw[t] = (cc < 0) ? 1 : ((cc >= W) ? W - 2 : cc);
    }

    const float* xb = x + (size_t)b * H * W * C;

    // 18 independent, fully-coalesced 128B line loads (lane = channel).
    float v[3][6];
#pragma unroll
    for (int dr = 0; dr < 3; dr++) {
        const float* rp = xb + (size_t)rh[dr] * W * C + lane;
#pragma unroll
        for (int t = 0; t < 6; t++) {
            v[dr][t] = rp[rw[t] * C];
        }
    }

    // Scatter in output order: s[p*288 + c*9 + (dr*3+dj)] = v[dr][p+dj].
    // Word index mod 32 = (lane*9 + i) mod 32: permutation over lanes -> no
    // bank conflicts.
    const int lb = lane * TAPS;
#pragma unroll
    for (int p = 0; p < PIX_PER_WARP; p++) {
#pragma unroll
        for (int dr = 0; dr < 3; dr++) {
#pragma unroll
            for (int dj = 0; dj < 3; dj++) {
                s[p * OUT_PER_PIX + lb + dr * 3 + dj] = v[dr][p + dj];
            }
        }
    }
    __syncwarp();

    // 4 pixels = 4608 contiguous bytes = 288 float4 = exactly 9 full-warp
    // STG.128 iterations. Streaming hint: output is never re-read; keep the
    // input resident in L2 instead.
    const size_t pix0 = (size_t)blockIdx.y * W + w0;
    float4* __restrict__ o4 = reinterpret_cast<float4*>(out + pix0 * OUT_PER_PIX);
    const float4* __restrict__ s4 = reinterpret_cast<const float4*>(s);
#pragma unroll
    for (int k = 0; k < 9; k++) {
        __stcs(o4 + k * 32 + lane, s4[k * 32 + lane]);
    }
}

extern "C" void kernel_launch(void* const* d_in, const int* in_sizes, int n_in,
                              void* d_out, int out_size) {
    const float* x = (const float*)d_in[0];
    float* out = (float*)d_out;
    (void)in_sizes; (void)n_in; (void)out_size;

    dim3 grid(W / (PIX_PER_WARP * WARPS_PER_BLOCK), B * H);  // (8, 2048)
    patch_extract_kernel<<<grid, THREADS>>>(x, out);
}

// round 5
// speedup vs baseline: 1.2593x; 1.0136x over previous
#include <cuda_runtime.h>
#include <cstdint>

// x: (8, 256, 256, 32) fp32, reflect-pad 3x3 patch extraction.
// out[b,h,w, c*9 + i] = x[b, reflect(h + i/3 - 1), reflect(w + i%3 - 1), c]
//
// Warp = 4-pixel strip along W:
//   - 18 coalesced 128B line loads (3 rows x 6 cols, lane = channel)
//   - register->smem scatter into final output order (stride-9 word scatter
//     is a permutation mod 32 banks -> conflict-free)
//   - ONE cp.async.bulk (TMA) smem->gmem copy of the 4608B contiguous block,
//     replacing the LDS.128 + STG.128 readback entirely.

static constexpr int B = 8;
static constexpr int H = 256;
static constexpr int W = 256;
static constexpr int C = 32;
static constexpr int TAPS = 9;
static constexpr int OUT_PER_PIX = C * TAPS;   // 288 floats = 1152 B
static constexpr int PIX_PER_WARP = 4;
static constexpr int BYTES_PER_WARP = PIX_PER_WARP * OUT_PER_PIX * 4;  // 4608
static constexpr int WARPS_PER_BLOCK = 8;
static constexpr int THREADS = WARPS_PER_BLOCK * 32;

__device__ __forceinline__ uint32_t smem_u32(const void* p) {
    uint32_t a;
    asm("{ .reg .u64 t; cvta.to.shared.u64 t, %1; cvt.u32.u64 %0, t; }"
        : "=r"(a) : "l"(p));
    return a;
}

__global__ __launch_bounds__(THREADS)
void patch_extract_kernel(const float* __restrict__ x, float* __restrict__ out) {
    const int warp = threadIdx.x >> 5;
    const int lane = threadIdx.x & 31;

    // blockIdx.y = b*H + h  (2048 rows); blockIdx.x = strip-group (8 per row)
    const int h = blockIdx.y & (H - 1);
    const int b = blockIdx.y >> 8;
    const int strip = blockIdx.x * WARPS_PER_BLOCK + warp;
    const int w0 = strip * PIX_PER_WARP;

    // Per-warp staging: 4 pixels x 1152 B = 4608 B, in final output order.
    __shared__ __align__(16) float sm[WARPS_PER_BLOCK][PIX_PER_WARP * OUT_PER_PIX];
    float* s = sm[warp];

    // Reflected rows (3) and columns (6: w0-1 .. w0+4). PAD=1: -1 -> 1, N -> N-2.
    int rh[3];
#pragma unroll
    for (int d = 0; d < 3; d++) {
        int r = h + d - 1;
        rh[d] = (r < 0) ? 1 : ((r >= H) ? H - 2 : r);
    }
    int rw[6];
#pragma unroll
    for (int t = 0; t < 6; t++) {
        int cc = w0 - 1 + t;
        rw[t] = (cc < 0) ? 1 : ((cc >= W) ? W - 2 : cc);
    }

    const float* xb = x + (size_t)b * H * W * C;

    // 18 independent, fully-coalesced 128B line loads (lane = channel).
    float v[3][6];
#pragma unroll
    for (int dr = 0; dr < 3; dr++) {
        const float* rp = xb + (size_t)rh[dr] * W * C + lane;
#pragma unroll
        for (int t = 0; t < 6; t++) {
            v[dr][t] = rp[rw[t] * C];
        }
    }

    // Scatter in output order: s[p*288 + c*9 + (dr*3+dj)] = v[dr][p+dj].
    const int lb = lane * TAPS;
#pragma unroll
    for (int p = 0; p < PIX_PER_WARP; p++) {
#pragma unroll
        for (int dr = 0; dr < 3; dr++) {
#pragma unroll
            for (int dj = 0; dj < 3; dj++) {
                s[p * OUT_PER_PIX + lb + dr * 3 + dj] = v[dr][p + dj];
            }
        }
    }
    __syncwarp();

    // One TMA bulk copy: smem (final order) -> gmem, 4608 B, 16B-aligned.
    if (lane == 0) {
        const size_t pix0 = (size_t)blockIdx.y * W + w0;
        float* gdst = out + pix0 * OUT_PER_PIX;
        const uint32_t saddr = smem_u32(s);
        asm volatile("fence.proxy.async.shared::cta;" ::: "memory");
        asm volatile(
            "cp.async.bulk.global.shared::cta.bulk_group [%0], [%1], %2;"
            :: "l"(gdst), "r"(saddr), "r"((uint32_t)BYTES_PER_WARP)
            : "memory");
        asm volatile("cp.async.bulk.commit_group;" ::: "memory");
        // Must complete before CTA exit (smem is deallocated on exit).
        asm volatile("cp.async.bulk.wait_group 0;" ::: "memory");
    }
}

extern "C" void kernel_launch(void* const* d_in, const int* in_sizes, int n_in,
                              void* d_out, int out_size) {
    const float* x = (const float*)d_in[0];
    float* out = (float*)d_out;
    (void)in_sizes; (void)n_in; (void)out_size;

    dim3 grid(W / (PIX_PER_WARP * WARPS_PER_BLOCK), B * H);  // (8, 2048)
    patch_extract_kernel<<<grid, THREADS>>>(x, out);
}